// round 1
// baseline (speedup 1.0000x reference)
#include <cuda_runtime.h>
#include <math.h>

#define B_ 4
#define L_ 2048
#define D_ 1024
#define BM 64
#define BN 64
#define BK 16

// log2(0.96875)
#define LOG2G (-0.04580373f)

// Scratch (allocation-free rule: __device__ globals)
__device__ float g_Q[B_ * L_ * D_];
__device__ float g_K[B_ * L_ * D_];
__device__ float g_V[B_ * L_ * D_];
__device__ float g_A[(size_t)B_ * L_ * L_];

// ---------------------------------------------------------------------------
// Projection GEMM: dst[M,N] = X[M,K] @ W[K,N], with optional xPos epilogue.
// MODE: 0 = V (plain), 1 = Q (xpos), 2 = K (xpos downscale)
// M = B_*L_ = 8192, N = K = 1024.
// ---------------------------------------------------------------------------
template <int MODE>
__global__ __launch_bounds__(256) void proj_kernel(const float* __restrict__ X,
                                                   const float* __restrict__ W) {
    __shared__ float As[BK][BM + 1];
    __shared__ float Bs[BK][BN];

    float* dst = (MODE == 1) ? g_Q : (MODE == 2 ? g_K : g_V);

    const int n0 = blockIdx.x * BN;
    const int m0 = blockIdx.y * BM;
    const int t = threadIdx.x;
    const int ty = t >> 4;   // 0..15
    const int tx = t & 15;   // 0..15

    float acc[4][4] = {};

    for (int k0 = 0; k0 < D_; k0 += BK) {
        // Load A tile (64 rows x 16 k), transposed into As
        {
            int row = t >> 2;           // 0..63
            int kc = (t & 3) * 4;       // 0,4,8,12
            float4 v = *reinterpret_cast<const float4*>(
                &X[(size_t)(m0 + row) * D_ + k0 + kc]);
            As[kc + 0][row] = v.x;
            As[kc + 1][row] = v.y;
            As[kc + 2][row] = v.z;
            As[kc + 3][row] = v.w;
        }
        // Load B tile (16 k x 64 n)
        {
            int kr = t >> 4;            // 0..15
            int nc = (t & 15) * 4;
            *reinterpret_cast<float4*>(&Bs[kr][nc]) =
                *reinterpret_cast<const float4*>(&W[(size_t)(k0 + kr) * D_ + n0 + nc]);
        }
        __syncthreads();

#pragma unroll
        for (int k = 0; k < BK; ++k) {
            float a[4], b[4];
#pragma unroll
            for (int i = 0; i < 4; ++i) a[i] = As[k][ty * 4 + i];
#pragma unroll
            for (int j = 0; j < 4; ++j) b[j] = Bs[k][tx * 4 + j];
#pragma unroll
            for (int i = 0; i < 4; ++i)
#pragma unroll
                for (int j = 0; j < 4; ++j) acc[i][j] += a[i] * b[j];
        }
        __syncthreads();
    }

    // Epilogue: write (+ xPos rotation for Q/K)
#pragma unroll
    for (int i = 0; i < 4; ++i) {
        int row = m0 + ty * 4 + i;          // global row over B*L
        int pos = row & (L_ - 1);           // position within sequence
#pragma unroll
        for (int jp = 0; jp < 2; ++jp) {
            int c0 = n0 + tx * 4 + jp * 2;  // even column
            float x0 = acc[i][jp * 2 + 0];
            float x1 = acc[i][jp * 2 + 1];
            if (MODE == 0) {
                dst[(size_t)row * D_ + c0 + 0] = x0;
                dst[(size_t)row * D_ + c0 + 1] = x1;
            } else {
                int h = c0 >> 1;
                float sv = ((float)c0 + 0.4f * (float)D_) / (1.4f * (float)D_);
                float e = (float)pos * (1.0f / 512.0f);
                float scale = powf(sv, (MODE == 1) ? e : -e);
                float invf = powf(10000.0f, -(float)h * (1.0f / 512.0f));
                float ang = (float)pos * invf;
                float s, c;
                sincosf(ang, &s, &c);
                s *= scale;
                c *= scale;
                dst[(size_t)row * D_ + c0 + 0] = x0 * c - x1 * s;
                dst[(size_t)row * D_ + c0 + 1] = x1 * c + x0 * s;
            }
        }
    }
}

// ---------------------------------------------------------------------------
// A = (Q @ K^T) * DecayMask, per batch. M = N = L_, K = D_.
// Tiles entirely above the diagonal are written as zeros without compute.
// ---------------------------------------------------------------------------
__global__ __launch_bounds__(256) void qk_kernel() {
    const int b = blockIdx.z;
    const int m0 = blockIdx.x * BN;  // key index
    const int n0 = blockIdx.y * BM;  // query index
    const float* Q = g_Q + (size_t)b * L_ * D_;
    const float* Kp = g_K + (size_t)b * L_ * D_;
    float* A = g_A + (size_t)b * L_ * L_;

    if (m0 >= n0 + BM) {
        // strictly upper triangle: all zeros
        for (int i = threadIdx.x; i < BM * (BN / 4); i += 256) {
            int r = i / (BN / 4);
            int c = (i % (BN / 4)) * 4;
            *reinterpret_cast<float4*>(&A[(size_t)(n0 + r) * L_ + m0 + c]) =
                make_float4(0.f, 0.f, 0.f, 0.f);
        }
        return;
    }

    __shared__ float Qs[BK][BM + 1];
    __shared__ float Ks[BK][BN + 1];

    const int t = threadIdx.x;
    const int ty = t >> 4;
    const int tx = t & 15;

    float acc[4][4] = {};

    for (int k0 = 0; k0 < D_; k0 += BK) {
        {
            int row = t >> 2;
            int kc = (t & 3) * 4;
            float4 v = *reinterpret_cast<const float4*>(
                &Q[(size_t)(n0 + row) * D_ + k0 + kc]);
            Qs[kc + 0][row] = v.x;
            Qs[kc + 1][row] = v.y;
            Qs[kc + 2][row] = v.z;
            Qs[kc + 3][row] = v.w;
        }
        {
            int row = t >> 2;
            int kc = (t & 3) * 4;
            float4 v = *reinterpret_cast<const float4*>(
                &Kp[(size_t)(m0 + row) * D_ + k0 + kc]);
            Ks[kc + 0][row] = v.x;
            Ks[kc + 1][row] = v.y;
            Ks[kc + 2][row] = v.z;
            Ks[kc + 3][row] = v.w;
        }
        __syncthreads();

#pragma unroll
        for (int k = 0; k < BK; ++k) {
            float a[4], bb[4];
#pragma unroll
            for (int i = 0; i < 4; ++i) a[i] = Qs[k][ty * 4 + i];
#pragma unroll
            for (int j = 0; j < 4; ++j) bb[j] = Ks[k][tx * 4 + j];
#pragma unroll
            for (int i = 0; i < 4; ++i)
#pragma unroll
                for (int j = 0; j < 4; ++j) acc[i][j] += a[i] * bb[j];
        }
        __syncthreads();
    }

#pragma unroll
    for (int i = 0; i < 4; ++i) {
        int n = n0 + ty * 4 + i;
#pragma unroll
        for (int j = 0; j < 4; ++j) {
            int m = m0 + tx * 4 + j;
            float v = 0.f;
            if (m <= n) {
                v = acc[i][j] * exp2f((float)(n - m) * LOG2G);
            }
            A[(size_t)n * L_ + m] = v;
        }
    }
}

// ---------------------------------------------------------------------------
// out = A @ V, per batch. M = L_, N = D_, reduction limited to causal extent.
// ---------------------------------------------------------------------------
__global__ __launch_bounds__(256) void av_kernel(float* __restrict__ out) {
    const int b = blockIdx.z;
    const int j0 = blockIdx.x * BN;
    const int n0 = blockIdx.y * BM;
    const float* A = g_A + (size_t)b * L_ * L_;
    const float* V = g_V + (size_t)b * L_ * D_;
    float* O = out + (size_t)b * L_ * D_;

    __shared__ float As[BK][BM + 1];
    __shared__ float Vs[BK][BN];

    const int t = threadIdx.x;
    const int ty = t >> 4;
    const int tx = t & 15;

    float acc[4][4] = {};

    const int kEnd = n0 + BM;  // A[n][m] == 0 for m > n, so stop at tile's max n
    for (int k0 = 0; k0 < kEnd; k0 += BK) {
        {
            int row = t >> 2;
            int kc = (t & 3) * 4;
            float4 v = *reinterpret_cast<const float4*>(
                &A[(size_t)(n0 + row) * L_ + k0 + kc]);
            As[kc + 0][row] = v.x;
            As[kc + 1][row] = v.y;
            As[kc + 2][row] = v.z;
            As[kc + 3][row] = v.w;
        }
        {
            int kr = t >> 4;
            int nc = (t & 15) * 4;
            *reinterpret_cast<float4*>(&Vs[kr][nc]) =
                *reinterpret_cast<const float4*>(&V[(size_t)(k0 + kr) * D_ + j0 + nc]);
        }
        __syncthreads();

#pragma unroll
        for (int k = 0; k < BK; ++k) {
            float a[4], bb[4];
#pragma unroll
            for (int i = 0; i < 4; ++i) a[i] = As[k][ty * 4 + i];
#pragma unroll
            for (int j = 0; j < 4; ++j) bb[j] = Vs[k][tx * 4 + j];
#pragma unroll
            for (int i = 0; i < 4; ++i)
#pragma unroll
                for (int j = 0; j < 4; ++j) acc[i][j] += a[i] * bb[j];
        }
        __syncthreads();
    }

#pragma unroll
    for (int i = 0; i < 4; ++i) {
        int r = n0 + ty * 4 + i;
#pragma unroll
        for (int j = 0; j < 4; ++j) {
            O[(size_t)r * D_ + j0 + tx * 4 + j] = acc[i][j];
        }
    }
}

// ---------------------------------------------------------------------------
extern "C" void kernel_launch(void* const* d_in, const int* in_sizes, int n_in,
                              void* d_out, int out_size) {
    const float* X = (const float*)d_in[0];
    const float* WQ = (const float*)d_in[1];
    const float* WK = (const float*)d_in[2];
    const float* WV = (const float*)d_in[3];
    float* out = (float*)d_out;

    dim3 pgrid(D_ / BN, (B_ * L_) / BM);   // 16 x 128
    proj_kernel<1><<<pgrid, 256>>>(X, WQ);
    proj_kernel<2><<<pgrid, 256>>>(X, WK);
    proj_kernel<0><<<pgrid, 256>>>(X, WV);

    dim3 qkgrid(L_ / BN, L_ / BM, B_);     // 32 x 32 x 4
    qk_kernel<<<qkgrid, 256>>>();

    dim3 avgrid(D_ / BN, L_ / BM, B_);     // 16 x 32 x 4
    av_kernel<<<avgrid, 256>>>(out);
}

// round 2
// speedup vs baseline: 1.0025x; 1.0025x over previous
#include <cuda_runtime.h>
#include <math.h>

#define B_ 4
#define L_ 2048
#define D_ 1024
#define BM 64
#define BN 64
#define BK 16

// log2(0.96875)
#define LOG2G (-0.04580373f)

// Scratch (allocation-free rule: __device__ globals)
__device__ float g_Q[B_ * L_ * D_];
__device__ float g_K[B_ * L_ * D_];
__device__ float g_V[B_ * L_ * D_];
__device__ float g_A[(size_t)B_ * L_ * L_];

// ---------------------------------------------------------------------------
// Projection GEMM: dst[M,N] = X[M,K] @ W[K,N], with optional xPos epilogue.
// MODE: 0 = V (plain), 1 = Q (xpos), 2 = K (xpos downscale)
// M = B_*L_ = 8192, N = K = 1024.
// ---------------------------------------------------------------------------
template <int MODE>
__global__ __launch_bounds__(256) void proj_kernel(const float* __restrict__ X,
                                                   const float* __restrict__ W) {
    __shared__ float As[BK][BM + 1];
    __shared__ float Bs[BK][BN];

    float* dst = (MODE == 1) ? g_Q : (MODE == 2 ? g_K : g_V);

    const int n0 = blockIdx.x * BN;
    const int m0 = blockIdx.y * BM;
    const int t = threadIdx.x;
    const int ty = t >> 4;   // 0..15
    const int tx = t & 15;   // 0..15

    float acc[4][4] = {};

    for (int k0 = 0; k0 < D_; k0 += BK) {
        // Load A tile (64 rows x 16 k), transposed into As
        {
            int row = t >> 2;           // 0..63
            int kc = (t & 3) * 4;       // 0,4,8,12
            float4 v = *reinterpret_cast<const float4*>(
                &X[(size_t)(m0 + row) * D_ + k0 + kc]);
            As[kc + 0][row] = v.x;
            As[kc + 1][row] = v.y;
            As[kc + 2][row] = v.z;
            As[kc + 3][row] = v.w;
        }
        // Load B tile (16 k x 64 n)
        {
            int kr = t >> 4;            // 0..15
            int nc = (t & 15) * 4;
            *reinterpret_cast<float4*>(&Bs[kr][nc]) =
                *reinterpret_cast<const float4*>(&W[(size_t)(k0 + kr) * D_ + n0 + nc]);
        }
        __syncthreads();

#pragma unroll
        for (int k = 0; k < BK; ++k) {
            float a[4], b[4];
#pragma unroll
            for (int i = 0; i < 4; ++i) a[i] = As[k][ty * 4 + i];
#pragma unroll
            for (int j = 0; j < 4; ++j) b[j] = Bs[k][tx * 4 + j];
#pragma unroll
            for (int i = 0; i < 4; ++i)
#pragma unroll
                for (int j = 0; j < 4; ++j) acc[i][j] += a[i] * b[j];
        }
        __syncthreads();
    }

    // Epilogue: write (+ xPos rotation for Q/K)
#pragma unroll
    for (int i = 0; i < 4; ++i) {
        int row = m0 + ty * 4 + i;          // global row over B*L
        int pos = row & (L_ - 1);           // position within sequence
#pragma unroll
        for (int jp = 0; jp < 2; ++jp) {
            int c0 = n0 + tx * 4 + jp * 2;  // even column
            float x0 = acc[i][jp * 2 + 0];
            float x1 = acc[i][jp * 2 + 1];
            if (MODE == 0) {
                dst[(size_t)row * D_ + c0 + 0] = x0;
                dst[(size_t)row * D_ + c0 + 1] = x1;
            } else {
                int h = c0 >> 1;
                float sv = ((float)c0 + 0.4f * (float)D_) / (1.4f * (float)D_);
                float e = (float)pos * (1.0f / 512.0f);
                float scale = powf(sv, (MODE == 1) ? e : -e);
                float invf = powf(10000.0f, -(float)h * (1.0f / 512.0f));
                float ang = (float)pos * invf;
                float s, c;
                sincosf(ang, &s, &c);
                s *= scale;
                c *= scale;
                dst[(size_t)row * D_ + c0 + 0] = x0 * c - x1 * s;
                dst[(size_t)row * D_ + c0 + 1] = x1 * c + x0 * s;
            }
        }
    }
}

// ---------------------------------------------------------------------------
// A = (Q @ K^T) * DecayMask, per batch. M = N = L_, K = D_.
// Tiles entirely above the diagonal are written as zeros without compute.
// ---------------------------------------------------------------------------
__global__ __launch_bounds__(256) void qk_kernel() {
    const int b = blockIdx.z;
    const int m0 = blockIdx.x * BN;  // key index
    const int n0 = blockIdx.y * BM;  // query index
    const float* Q = g_Q + (size_t)b * L_ * D_;
    const float* Kp = g_K + (size_t)b * L_ * D_;
    float* A = g_A + (size_t)b * L_ * L_;

    if (m0 >= n0 + BM) {
        // strictly upper triangle: all zeros
        for (int i = threadIdx.x; i < BM * (BN / 4); i += 256) {
            int r = i / (BN / 4);
            int c = (i % (BN / 4)) * 4;
            *reinterpret_cast<float4*>(&A[(size_t)(n0 + r) * L_ + m0 + c]) =
                make_float4(0.f, 0.f, 0.f, 0.f);
        }
        return;
    }

    __shared__ float Qs[BK][BM + 1];
    __shared__ float Ks[BK][BN + 1];

    const int t = threadIdx.x;
    const int ty = t >> 4;
    const int tx = t & 15;

    float acc[4][4] = {};

    for (int k0 = 0; k0 < D_; k0 += BK) {
        {
            int row = t >> 2;
            int kc = (t & 3) * 4;
            float4 v = *reinterpret_cast<const float4*>(
                &Q[(size_t)(n0 + row) * D_ + k0 + kc]);
            Qs[kc + 0][row] = v.x;
            Qs[kc + 1][row] = v.y;
            Qs[kc + 2][row] = v.z;
            Qs[kc + 3][row] = v.w;
        }
        {
            int row = t >> 2;
            int kc = (t & 3) * 4;
            float4 v = *reinterpret_cast<const float4*>(
                &Kp[(size_t)(m0 + row) * D_ + k0 + kc]);
            Ks[kc + 0][row] = v.x;
            Ks[kc + 1][row] = v.y;
            Ks[kc + 2][row] = v.z;
            Ks[kc + 3][row] = v.w;
        }
        __syncthreads();

#pragma unroll
        for (int k = 0; k < BK; ++k) {
            float a[4], bb[4];
#pragma unroll
            for (int i = 0; i < 4; ++i) a[i] = Qs[k][ty * 4 + i];
#pragma unroll
            for (int j = 0; j < 4; ++j) bb[j] = Ks[k][tx * 4 + j];
#pragma unroll
            for (int i = 0; i < 4; ++i)
#pragma unroll
                for (int j = 0; j < 4; ++j) acc[i][j] += a[i] * bb[j];
        }
        __syncthreads();
    }

#pragma unroll
    for (int i = 0; i < 4; ++i) {
        int n = n0 + ty * 4 + i;
#pragma unroll
        for (int j = 0; j < 4; ++j) {
            int m = m0 + tx * 4 + j;
            float v = 0.f;
            if (m <= n) {
                v = acc[i][j] * exp2f((float)(n - m) * LOG2G);
            }
            A[(size_t)n * L_ + m] = v;
        }
    }
}

// ---------------------------------------------------------------------------
// out = A @ V, per batch. M = L_, N = D_, reduction limited to causal extent.
// ---------------------------------------------------------------------------
__global__ __launch_bounds__(256) void av_kernel(float* __restrict__ out) {
    const int b = blockIdx.z;
    const int j0 = blockIdx.x * BN;
    const int n0 = blockIdx.y * BM;
    const float* A = g_A + (size_t)b * L_ * L_;
    const float* V = g_V + (size_t)b * L_ * D_;
    float* O = out + (size_t)b * L_ * D_;

    __shared__ float As[BK][BM + 1];
    __shared__ float Vs[BK][BN];

    const int t = threadIdx.x;
    const int ty = t >> 4;
    const int tx = t & 15;

    float acc[4][4] = {};

    const int kEnd = n0 + BM;  // A[n][m] == 0 for m > n, so stop at tile's max n
    for (int k0 = 0; k0 < kEnd; k0 += BK) {
        {
            int row = t >> 2;
            int kc = (t & 3) * 4;
            float4 v = *reinterpret_cast<const float4*>(
                &A[(size_t)(n0 + row) * L_ + k0 + kc]);
            As[kc + 0][row] = v.x;
            As[kc + 1][row] = v.y;
            As[kc + 2][row] = v.z;
            As[kc + 3][row] = v.w;
        }
        {
            int kr = t >> 4;
            int nc = (t & 15) * 4;
            *reinterpret_cast<float4*>(&Vs[kr][nc]) =
                *reinterpret_cast<const float4*>(&V[(size_t)(k0 + kr) * D_ + j0 + nc]);
        }
        __syncthreads();

#pragma unroll
        for (int k = 0; k < BK; ++k) {
            float a[4], bb[4];
#pragma unroll
            for (int i = 0; i < 4; ++i) a[i] = As[k][ty * 4 + i];
#pragma unroll
            for (int j = 0; j < 4; ++j) bb[j] = Vs[k][tx * 4 + j];
#pragma unroll
            for (int i = 0; i < 4; ++i)
#pragma unroll
                for (int j = 0; j < 4; ++j) acc[i][j] += a[i] * bb[j];
        }
        __syncthreads();
    }

#pragma unroll
    for (int i = 0; i < 4; ++i) {
        int r = n0 + ty * 4 + i;
#pragma unroll
        for (int j = 0; j < 4; ++j) {
            O[(size_t)r * D_ + j0 + tx * 4 + j] = acc[i][j];
        }
    }
}

// ---------------------------------------------------------------------------
extern "C" void kernel_launch(void* const* d_in, const int* in_sizes, int n_in,
                              void* d_out, int out_size) {
    const float* X = (const float*)d_in[0];
    const float* WQ = (const float*)d_in[1];
    const float* WK = (const float*)d_in[2];
    const float* WV = (const float*)d_in[3];
    float* out = (float*)d_out;

    dim3 pgrid(D_ / BN, (B_ * L_) / BM);   // 16 x 128
    proj_kernel<1><<<pgrid, 256>>>(X, WQ);
    proj_kernel<2><<<pgrid, 256>>>(X, WK);
    proj_kernel<0><<<pgrid, 256>>>(X, WV);

    dim3 qkgrid(L_ / BN, L_ / BM, B_);     // 32 x 32 x 4
    qk_kernel<<<qkgrid, 256>>>();

    dim3 avgrid(D_ / BN, L_ / BM, B_);     // 16 x 32 x 4
    av_kernel<<<avgrid, 256>>>(out);
}

// round 4
// speedup vs baseline: 2.4797x; 2.4734x over previous
#include <cuda_runtime.h>
#include <cuda_bf16.h>
#include <stdint.h>
#include <math.h>

#define B_ 4
#define L_ 2048
#define D_ 1024
#define NBL (B_ * L_)

#define LOG2G  (-0.045803734f)          // log2(0.96875)
#define L2_1E4 (13.287712379549449f)    // log2(10000)

// ------------------- global scratch (allocation-free rule) -------------------
__device__ __align__(16) __nv_bfloat16 g_Xh[NBL * D_], g_Xl[NBL * D_];
__device__ __align__(16) __nv_bfloat16 g_Wh[3][D_ * D_], g_Wl[3][D_ * D_];
__device__ __align__(16) __nv_bfloat16 g_Qh[NBL * D_], g_Ql[NBL * D_];
__device__ __align__(16) __nv_bfloat16 g_Kh[NBL * D_], g_Kl[NBL * D_];
__device__ __align__(16) __nv_bfloat16 g_Vh[NBL * D_], g_Vl[NBL * D_];
__device__ __align__(16) __nv_bfloat16 g_Th[NBL * D_], g_Tl[NBL * D_];  // V^T
__device__ __align__(16) __nv_bfloat16 g_Ah[(size_t)B_ * L_ * L_];
__device__ __align__(16) __nv_bfloat16 g_Al[(size_t)B_ * L_ * L_];
__device__ __align__(16) float4 g_xt[(size_t)L_ * (D_ / 2)];  // cQ,sQ,cK,sK

// ------------------------------- helpers -------------------------------------
__device__ __forceinline__ uint32_t smem_u32(const void* p) {
    uint32_t a;
    asm("{ .reg .u64 t; cvta.to.shared.u64 t, %1; cvt.u32.u64 %0, t; }"
        : "=r"(a) : "l"(p));
    return a;
}

__device__ __forceinline__ void ldm4(uint32_t* r, uint32_t a) {
    asm volatile("ldmatrix.sync.aligned.m8n8.x4.shared.b16 {%0,%1,%2,%3}, [%4];"
                 : "=r"(r[0]), "=r"(r[1]), "=r"(r[2]), "=r"(r[3]) : "r"(a));
}

__device__ __forceinline__ void mma_bf16(float* c, const uint32_t* a, const uint32_t* b) {
    asm volatile(
        "mma.sync.aligned.m16n8k16.row.col.f32.bf16.bf16.f32 "
        "{%0,%1,%2,%3}, {%4,%5,%6,%7}, {%8,%9}, {%0,%1,%2,%3};"
        : "+f"(c[0]), "+f"(c[1]), "+f"(c[2]), "+f"(c[3])
        : "r"(a[0]), "r"(a[1]), "r"(a[2]), "r"(a[3]), "r"(b[0]), "r"(b[1]));
}

// bf16 hi/lo split of two floats, packed as bf16x2 words
__device__ __forceinline__ void split2(float a, float b, uint32_t& hi, uint32_t& lo) {
    __nv_bfloat16 ha = __float2bfloat16(a);
    __nv_bfloat16 hb = __float2bfloat16(b);
    __nv_bfloat16 la = __float2bfloat16(a - __bfloat162float(ha));
    __nv_bfloat16 lb = __float2bfloat16(b - __bfloat162float(hb));
    __nv_bfloat162 H;  H.x = ha; H.y = hb;
    __nv_bfloat162 Lo; Lo.x = la; Lo.y = lb;
    hi = *reinterpret_cast<uint32_t*>(&H);
    lo = *reinterpret_cast<uint32_t*>(&Lo);
}

// copy 128 rows x 32 cols bf16 tile, gmem(stride ld) -> smem(stride 40), 256 thr
__device__ __forceinline__ void ldtile(__nv_bfloat16* s,
                                       const __nv_bfloat16* __restrict__ g,
                                       int ld, int t) {
#pragma unroll
    for (int it = 0; it < 2; ++it) {
        int idx = t + it * 256;
        int r = idx >> 2, sg = (idx & 3) << 3;
        *reinterpret_cast<float4*>(s + r * 40 + sg) =
            *reinterpret_cast<const float4*>(g + (size_t)r * ld + sg);
    }
}

// -------------------- CTA 128x128 GEMM mainloop (bf16 split) -----------------
// acc layout per warp: [mtile 0..1][ntile 0..7][c0..c3] (m16n8k16 fragments)
__device__ __forceinline__ void gemm_loop(
    float acc[2][8][4],
    const __nv_bfloat16* __restrict__ Agh, const __nv_bfloat16* __restrict__ Agl,
    const __nv_bfloat16* __restrict__ Bgh, const __nv_bfloat16* __restrict__ Bgl,
    int lda, int ldb, int nchunks, __nv_bfloat16* sm, int t) {
    __nv_bfloat16* sAh = sm;
    __nv_bfloat16* sAl = sm + 5120;
    __nv_bfloat16* sBh = sm + 10240;
    __nv_bfloat16* sBl = sm + 15360;

    const int lane = t & 31, w = t >> 5;
    const int wm0 = (w >> 1) << 5;   // warp m offset (0,32,64,96)
    const int wn0 = (w & 1) << 6;    // warp n offset (0,64)

    // ldmatrix per-thread row addresses (bytes), k0 added inside
    const int arow = wm0 + (lane & 15);
    const int acol = (lane >> 4) << 3;
    const uint32_t aH = smem_u32(sAh) + (uint32_t)(arow * 40 + acol) * 2;
    const uint32_t aL = aH + 10240;
    const int brow = wn0 + ((lane >> 4) << 3) + (lane & 7);
    const int bcol = ((lane >> 3) & 1) << 3;
    const uint32_t bH = smem_u32(sBh) + (uint32_t)(brow * 40 + bcol) * 2;
    const uint32_t bL = bH + 10240;

    for (int ch = 0; ch < nchunks; ++ch) {
        const int k0 = ch * 32;
        ldtile(sAh, Agh + k0, lda, t);
        ldtile(sAl, Agl + k0, lda, t);
        ldtile(sBh, Bgh + k0, ldb, t);
        ldtile(sBl, Bgl + k0, ldb, t);
        __syncthreads();

#pragma unroll
        for (int kk = 0; kk < 2; ++kk) {
            const uint32_t kb = kk * 32;  // 16 halves = 32 bytes
            uint32_t af[2][2][4], bf[2][8][2];
#pragma unroll
            for (int i = 0; i < 2; ++i) {
                ldm4(af[0][i], aH + i * 16 * 80 + kb);
                ldm4(af[1][i], aL + i * 16 * 80 + kb);
            }
#pragma unroll
            for (int jp = 0; jp < 4; ++jp) {
                uint32_t tp[4];
                ldm4(tp, bH + jp * 16 * 80 + kb);
                bf[0][2 * jp][0] = tp[0]; bf[0][2 * jp][1] = tp[1];
                bf[0][2 * jp + 1][0] = tp[2]; bf[0][2 * jp + 1][1] = tp[3];
                ldm4(tp, bL + jp * 16 * 80 + kb);
                bf[1][2 * jp][0] = tp[0]; bf[1][2 * jp][1] = tp[1];
                bf[1][2 * jp + 1][0] = tp[2]; bf[1][2 * jp + 1][1] = tp[3];
            }
#pragma unroll
            for (int i = 0; i < 2; ++i)
#pragma unroll
                for (int j = 0; j < 8; ++j) {
                    mma_bf16(acc[i][j], af[0][i], bf[0][j]);
                    mma_bf16(acc[i][j], af[0][i], bf[1][j]);
                    mma_bf16(acc[i][j], af[1][i], bf[0][j]);
                }
        }
        __syncthreads();
    }
}

// ------------------------------- prep kernels --------------------------------
__global__ __launch_bounds__(256) void cvt_x_kernel(const float* __restrict__ X) {
    size_t i = ((size_t)blockIdx.x * 256 + threadIdx.x) * 4;
    float4 v = *reinterpret_cast<const float4*>(X + i);
    uint32_t h0, l0, h1, l1;
    split2(v.x, v.y, h0, l0);
    split2(v.z, v.w, h1, l1);
    uint2 H; H.x = h0; H.y = h1;
    uint2 L; L.x = l0; L.y = l1;
    *reinterpret_cast<uint2*>(g_Xh + i) = H;
    *reinterpret_cast<uint2*>(g_Xl + i) = L;
}

// transpose + split W[k][n] -> Wt[n][k]
template <int S>
__global__ __launch_bounds__(256) void wt_kernel(const float* __restrict__ W) {
    __shared__ float ts[32][33];
    int n0 = blockIdx.x * 32, k0 = blockIdx.y * 32;
    int tx = threadIdx.x & 31, ty = threadIdx.x >> 5;
#pragma unroll
    for (int j = 0; j < 4; ++j)
        ts[ty + 8 * j][tx] = W[(size_t)(k0 + ty + 8 * j) * D_ + n0 + tx];
    __syncthreads();
#pragma unroll
    for (int j = 0; j < 4; ++j) {
        float v = ts[tx][ty + 8 * j];
        __nv_bfloat16 h = __float2bfloat16(v);
        __nv_bfloat16 l = __float2bfloat16(v - __bfloat162float(h));
        size_t o = (size_t)(n0 + ty + 8 * j) * D_ + k0 + tx;
        g_Wh[S][o] = h;
        g_Wl[S][o] = l;
    }
}

// transpose V[l][d] -> Vt[d][l] (hi and lo)
__global__ __launch_bounds__(256) void vt_kernel() {
    __shared__ __nv_bfloat16 ts[32][34];
    int b = blockIdx.z;
    int l0 = blockIdx.x * 32, d0 = blockIdx.y * 32;
    int tx = threadIdx.x & 31, ty = threadIdx.x >> 5;
#pragma unroll
    for (int a = 0; a < 2; ++a) {
        const __nv_bfloat16* s = (a ? g_Vl : g_Vh) + (size_t)b * L_ * D_;
        __nv_bfloat16* d = (a ? g_Tl : g_Th) + (size_t)b * L_ * D_;
        if (a) __syncthreads();
#pragma unroll
        for (int j = 0; j < 4; ++j)
            ts[ty + 8 * j][tx] = s[(size_t)(l0 + ty + 8 * j) * D_ + d0 + tx];
        __syncthreads();
#pragma unroll
        for (int j = 0; j < 4; ++j)
            d[(size_t)(d0 + ty + 8 * j) * L_ + l0 + tx] = ts[tx][ty + 8 * j];
    }
}

// precompute xPos rotation table: (cos*sc, sin*sc, cos/sc, sin/sc) per (pos, pair)
__global__ __launch_bounds__(256) void xt_kernel() {
    int idx = blockIdx.x * 256 + threadIdx.x;  // pos*512 + cp
    int pos = idx >> 9;
    int cp = idx & 511;
    float sv = (2.0f * cp + 409.6f) * (1.0f / 1433.6f);
    float sc = exp2f((float)pos * (1.0f / 512.0f) * log2f(sv));
    float invf = exp2f(-(float)cp * (L2_1E4 / 512.0f));
    float s, c;
    sincosf((float)pos * invf, &s, &c);
    g_xt[idx] = make_float4(c * sc, s * sc, c / sc, s / sc);
}

// ----------------------- projection GEMMs (Q / K / V) ------------------------
template <int MODE>  // 0=Q, 1=K, 2=V
__global__ __launch_bounds__(256) void proj_mm() {
    __shared__ __nv_bfloat16 sm[20480];
    float acc[2][8][4] = {};
    const int t = threadIdx.x;
    const int n0 = blockIdx.x << 7, m0 = blockIdx.y << 7;

    gemm_loop(acc,
              g_Xh + (size_t)m0 * D_, g_Xl + (size_t)m0 * D_,
              g_Wh[MODE] + (size_t)n0 * D_, g_Wl[MODE] + (size_t)n0 * D_,
              D_, D_, D_ / 32, sm, t);

    const int lane = t & 31, w = t >> 5;
    const int wm0 = (w >> 1) << 5, wn0 = (w & 1) << 6;
    const int rf = lane >> 2, cf = (lane & 3) << 1;
    __nv_bfloat16* dh = (MODE == 0) ? g_Qh : (MODE == 1 ? g_Kh : g_Vh);
    __nv_bfloat16* dl = (MODE == 0) ? g_Ql : (MODE == 1 ? g_Kl : g_Vl);

#pragma unroll
    for (int i = 0; i < 2; ++i)
#pragma unroll
        for (int hf = 0; hf < 2; ++hf) {
            int row = m0 + wm0 + i * 16 + rf + hf * 8;
            int pos = row & (L_ - 1);
#pragma unroll
            for (int j = 0; j < 8; ++j) {
                int col = n0 + wn0 + j * 8 + cf;
                float x0 = acc[i][j][hf * 2], x1 = acc[i][j][hf * 2 + 1];
                float y0, y1;
                if (MODE == 2) {
                    y0 = x0; y1 = x1;
                } else {
                    float4 tb = g_xt[(size_t)pos * 512 + (col >> 1)];
                    float c = (MODE == 0) ? tb.x : tb.z;
                    float s = (MODE == 0) ? tb.y : tb.w;
                    y0 = x0 * c - x1 * s;
                    y1 = x1 * c + x0 * s;
                }
                uint32_t h, l;
                split2(y0, y1, h, l);
                *reinterpret_cast<uint32_t*>(dh + (size_t)row * D_ + col) = h;
                *reinterpret_cast<uint32_t*>(dl + (size_t)row * D_ + col) = l;
            }
        }
}

// -------------------- A = (Q K^T) * decay, bf16 hi/lo ------------------------
__global__ __launch_bounds__(256) void qk_mm() {
    __shared__ __nv_bfloat16 sm[20480];
    __shared__ float pw[128], ipw[128];
    const int t = threadIdx.x;
    const int b = blockIdx.z;
    const int m0 = blockIdx.x << 7;  // keys
    const int n0 = blockIdx.y << 7;  // queries
    if (m0 >= n0 + 128) return;      // strictly-causal tile: never read by av

    if (t < 128) {
        pw[t] = exp2f((float)t * LOG2G);
        ipw[t] = exp2f(-(float)t * LOG2G);
    }

    float acc[2][8][4] = {};
    gemm_loop(acc,
              g_Qh + (size_t)(b * L_ + n0) * D_, g_Ql + (size_t)(b * L_ + n0) * D_,
              g_Kh + (size_t)(b * L_ + m0) * D_, g_Kl + (size_t)(b * L_ + m0) * D_,
              D_, D_, D_ / 32, sm, t);

    const int lane = t & 31, w = t >> 5;
    const int wm0 = (w >> 1) << 5, wn0 = (w & 1) << 6;
    const int rf = lane >> 2, cf = (lane & 3) << 1;
    const float base = exp2f((float)(n0 - m0) * LOG2G);
    __nv_bfloat16* Ah = g_Ah + (size_t)b * L_ * L_;
    __nv_bfloat16* Al = g_Al + (size_t)b * L_ * L_;

#pragma unroll
    for (int i = 0; i < 2; ++i)
#pragma unroll
        for (int hf = 0; hf < 2; ++hf) {
            int r = wm0 + i * 16 + rf + hf * 8;
            int gn = n0 + r;
            float bp = base * pw[r];
#pragma unroll
            for (int j = 0; j < 8; ++j) {
                int c = wn0 + j * 8 + cf;
                int gm = m0 + c;
                float v0 = (gm <= gn) ? acc[i][j][hf * 2] * (bp * ipw[c]) : 0.f;
                float v1 = (gm + 1 <= gn) ? acc[i][j][hf * 2 + 1] * (bp * ipw[c + 1]) : 0.f;
                uint32_t h, l;
                split2(v0, v1, h, l);
                *reinterpret_cast<uint32_t*>(Ah + (size_t)gn * L_ + gm) = h;
                *reinterpret_cast<uint32_t*>(Al + (size_t)gn * L_ + gm) = l;
            }
        }
}

// ------------------------------ out = A @ V ----------------------------------
__global__ __launch_bounds__(256) void av_mm(float* __restrict__ out) {
    __shared__ __nv_bfloat16 sm[20480];
    const int t = threadIdx.x;
    const int b = blockIdx.z;
    const int j0 = blockIdx.x << 7;  // output features
    const int n0 = blockIdx.y << 7;  // rows
    const int chunks = (blockIdx.y + 1) * 4;  // causal K-extent / 32

    float acc[2][8][4] = {};
    gemm_loop(acc,
              g_Ah + ((size_t)b * L_ + n0) * L_, g_Al + ((size_t)b * L_ + n0) * L_,
              g_Th + (size_t)b * L_ * D_ + (size_t)j0 * L_,
              g_Tl + (size_t)b * L_ * D_ + (size_t)j0 * L_,
              L_, L_, chunks, sm, t);

    const int lane = t & 31, w = t >> 5;
    const int wm0 = (w >> 1) << 5, wn0 = (w & 1) << 6;
    const int rf = lane >> 2, cf = (lane & 3) << 1;

#pragma unroll
    for (int i = 0; i < 2; ++i)
#pragma unroll
        for (int hf = 0; hf < 2; ++hf) {
            int row = n0 + wm0 + i * 16 + rf + hf * 8;
#pragma unroll
            for (int j = 0; j < 8; ++j) {
                int col = j0 + wn0 + j * 8 + cf;
                float2 v;
                v.x = acc[i][j][hf * 2];
                v.y = acc[i][j][hf * 2 + 1];
                *reinterpret_cast<float2*>(out + ((size_t)(b * L_ + row)) * D_ + col) = v;
            }
        }
}

// -----------------------------------------------------------------------------
extern "C" void kernel_launch(void* const* d_in, const int* in_sizes, int n_in,
                              void* d_out, int out_size) {
    const float* X = (const float*)d_in[0];
    const float* WQ = (const float*)d_in[1];
    const float* WK = (const float*)d_in[2];
    const float* WV = (const float*)d_in[3];
    float* out = (float*)d_out;

    cvt_x_kernel<<<(NBL * D_) / 1024, 256>>>(X);
    dim3 wg(32, 32);
    wt_kernel<0><<<wg, 256>>>(WQ);
    wt_kernel<1><<<wg, 256>>>(WK);
    wt_kernel<2><<<wg, 256>>>(WV);
    xt_kernel<<<(L_ * 512) / 256, 256>>>();

    proj_mm<0><<<dim3(8, 64), 256>>>();
    proj_mm<1><<<dim3(8, 64), 256>>>();
    proj_mm<2><<<dim3(8, 64), 256>>>();
    vt_kernel<<<dim3(64, 32, B_), 256>>>();

    qk_mm<<<dim3(16, 16, B_), 256>>>();
    av_mm<<<dim3(8, 16, B_), 256>>>(out);
}